// round 5
// baseline (speedup 1.0000x reference)
#include <cuda_runtime.h>

#define N_NODES 100000
#define F_IN    256
#define F_HID   64
#define F_OUT   40

// Scratch (static device globals — no allocation allowed)
__device__ float g_dis[N_NODES];              // deg accumulator, then rsqrt(deg+1)
__device__ float g_h1[N_NODES * F_HID];       // x @ W1
__device__ float g_agg1[N_NODES * F_HID];     // aggregated layer-1 (pre-relu, no self-loop)
__device__ float g_h2[N_NODES * F_OUT];       // relu_out @ W2

// ---------------------------------------------------------------------------
// Degree / normalization
// ---------------------------------------------------------------------------
__global__ void k_zero_deg(int n) {
    int i = blockIdx.x * blockDim.x + threadIdx.x;
    if (i < n) g_dis[i] = 0.0f;
}

__global__ void k_deg(const int* __restrict__ ei,
                      const float* __restrict__ ew, int E) {
    int e = blockIdx.x * blockDim.x + threadIdx.x;
    if (e < E) {
        int c = ei[E + e];
        atomicAdd(&g_dis[c], ew[e]);
    }
}

__global__ void k_dis(int n) {
    int i = blockIdx.x * blockDim.x + threadIdx.x;
    if (i < n) g_dis[i] = rsqrtf(g_dis[i] + 1.0f);   // +1 = self-loop weight
}

// ---------------------------------------------------------------------------
// GEMM1: g_h1[N,64] = x[N,256] @ W1[256,64]
// 256 threads, tile 256 rows x 64 cols, each thread 8x8 outputs.
// smem k-major. Per k-step: 4x LDS.128 feeds 64 FMA (0.75 B/FMA).
// ---------------------------------------------------------------------------
#define G1_ROWS 256
#define G1_KCH  32

__global__ void k_gemm1(const float* __restrict__ x,
                        const float* __restrict__ W1) {
    __shared__ float xs[G1_KCH][G1_ROWS];   // 32 KB
    __shared__ float ws[G1_KCH][F_HID];     // 8 KB

    int t    = threadIdx.x;
    int row0 = blockIdx.x * G1_ROWS;
    int tx   = t & 7;         // col group: cols tx*8 .. +7
    int ty   = t >> 3;        // row group: rows ty*8 .. +7

    float acc[8][8];
    #pragma unroll
    for (int i = 0; i < 8; i++)
        #pragma unroll
        for (int j = 0; j < 8; j++) acc[i][j] = 0.0f;

    for (int kc = 0; kc < F_IN / G1_KCH; kc++) {
        // W chunk: 32x64 floats = 512 float4 (W1 is k-major already)
        const float4* w4 = (const float4*)(W1 + kc * G1_KCH * F_HID);
        ((float4*)ws)[t]       = w4[t];
        ((float4*)ws)[t + 256] = w4[t + 256];
        // x tile: 256 rows x 32 k = 2048 float4, transposed into xs[k][row]
        #pragma unroll
        for (int j = 0; j < 8; j++) {
            int idx = t + j * 256;
            int r   = idx & 255;
            int kq  = idx >> 8;                  // 0..7
            int gr  = row0 + r;
            if (gr >= N_NODES) gr = N_NODES - 1; // clamped read (result discarded)
            float4 v = *(const float4*)(x + (size_t)gr * F_IN + kc * G1_KCH + kq * 4);
            xs[kq * 4 + 0][r] = v.x;
            xs[kq * 4 + 1][r] = v.y;
            xs[kq * 4 + 2][r] = v.z;
            xs[kq * 4 + 3][r] = v.w;
        }
        __syncthreads();

        #pragma unroll
        for (int kk = 0; kk < G1_KCH; kk++) {
            float4 a0 = *(const float4*)&xs[kk][ty * 8];
            float4 a1 = *(const float4*)&xs[kk][ty * 8 + 4];
            float4 b0 = *(const float4*)&ws[kk][tx * 8];
            float4 b1 = *(const float4*)&ws[kk][tx * 8 + 4];
            float av[8] = {a0.x, a0.y, a0.z, a0.w, a1.x, a1.y, a1.z, a1.w};
            float bv[8] = {b0.x, b0.y, b0.z, b0.w, b1.x, b1.y, b1.z, b1.w};
            #pragma unroll
            for (int i = 0; i < 8; i++)
                #pragma unroll
                for (int j = 0; j < 8; j++)
                    acc[i][j] += av[i] * bv[j];
        }
        __syncthreads();
    }

    #pragma unroll
    for (int i = 0; i < 8; i++) {
        int gr = row0 + ty * 8 + i;
        if (gr < N_NODES) {
            float* o = g_h1 + (size_t)gr * F_HID + tx * 8;
            *(float4*)(o)     = make_float4(acc[i][0], acc[i][1], acc[i][2], acc[i][3]);
            *(float4*)(o + 4) = make_float4(acc[i][4], acc[i][5], acc[i][6], acc[i][7]);
        }
    }
}

// ---------------------------------------------------------------------------
// Layer-1 edge aggregation: 16 threads per edge, float4 vectorized atomics
// ---------------------------------------------------------------------------
__global__ void k_zero_agg1(int n4) {
    int i = blockIdx.x * blockDim.x + threadIdx.x;
    if (i < n4) ((float4*)g_agg1)[i] = make_float4(0.f, 0.f, 0.f, 0.f);
}

__global__ void k_agg1(const int* __restrict__ ei,
                       const float* __restrict__ ew, int E) {
    int idx = blockIdx.x * blockDim.x + threadIdx.x;
    int e = idx >> 4;
    int c = idx & 15;
    if (e >= E) return;
    int r   = ei[e];
    int col = ei[E + e];
    float nrm = g_dis[r] * ew[e] * g_dis[col];
    float4 v = *(const float4*)(g_h1 + (size_t)r * F_HID + c * 4);
    atomicAdd((float4*)(g_agg1 + (size_t)col * F_HID + c * 4),
              make_float4(nrm * v.x, nrm * v.y, nrm * v.z, nrm * v.w));
}

// ---------------------------------------------------------------------------
// GEMM2 (fused): relu_in = max(agg1 + d^2*h1 + b1, 0) computed at load;
//                h2 = relu_in @ W2 stored to g_h2 AND out = b2 + d^2*h2.
// 256 thr, tile 128 rows x 40 cols, each thread 4x5, full K=64 in smem.
// ---------------------------------------------------------------------------
#define G2_ROWS 128

__global__ void k_gemm2(const float* __restrict__ W2,
                        const float* __restrict__ b1,
                        const float* __restrict__ b2,
                        float* __restrict__ out) {
    __shared__ float rs[F_HID][G2_ROWS];   // 32 KB, k-major
    __shared__ float ws2[F_HID][F_OUT];    // 10 KB
    __shared__ float b1s[F_HID];
    __shared__ float diss[G2_ROWS];        // d^2 per row

    int t    = threadIdx.x;
    int row0 = blockIdx.x * G2_ROWS;
    int tx   = t & 7;         // col group: cols tx*5 .. +4
    int ty   = t >> 3;        // row group: rows ty*4 .. +3

    if (t < F_HID) b1s[t] = b1[t];
    if (t < G2_ROWS) {
        int gr = row0 + t;
        if (gr >= N_NODES) gr = N_NODES - 1;
        float d = g_dis[gr];
        diss[t] = d * d;
    }
    // load W2 (2560 floats = 640 float4)
    #pragma unroll
    for (int j = 0; j < 3; j++) {
        int i = t + j * 256;
        if (i < 640) ((float4*)ws2)[i] = ((const float4*)W2)[i];
    }
    __syncthreads();   // b1s/diss ready before fused load below

    // load tile: relu(agg1 + d^2*h1 + b1), 128 rows x 64 k, transposed
    #pragma unroll
    for (int j = 0; j < 8; j++) {
        int idx = t + j * 256;
        int r   = idx & 127;
        int kq  = idx >> 7;                   // 0..15
        int gr  = row0 + r;
        if (gr >= N_NODES) gr = N_NODES - 1;
        float s = diss[r];
        float4 a = *(const float4*)(g_agg1 + (size_t)gr * F_HID + kq * 4);
        float4 h = *(const float4*)(g_h1   + (size_t)gr * F_HID + kq * 4);
        float4 b = *(const float4*)(b1s + kq * 4);
        rs[kq * 4 + 0][r] = fmaxf(a.x + s * h.x + b.x, 0.0f);
        rs[kq * 4 + 1][r] = fmaxf(a.y + s * h.y + b.y, 0.0f);
        rs[kq * 4 + 2][r] = fmaxf(a.z + s * h.z + b.z, 0.0f);
        rs[kq * 4 + 3][r] = fmaxf(a.w + s * h.w + b.w, 0.0f);
    }
    __syncthreads();

    float acc[4][5];
    #pragma unroll
    for (int i = 0; i < 4; i++)
        #pragma unroll
        for (int j = 0; j < 5; j++) acc[i][j] = 0.0f;

    #pragma unroll
    for (int kk = 0; kk < F_HID; kk++) {
        float4 a = *(const float4*)&rs[kk][ty * 4];
        float av[4] = {a.x, a.y, a.z, a.w};
        #pragma unroll
        for (int j = 0; j < 5; j++) {
            float b = ws2[kk][tx * 5 + j];
            #pragma unroll
            for (int i = 0; i < 4; i++)
                acc[i][j] += av[i] * b;
        }
    }

    #pragma unroll
    for (int i = 0; i < 4; i++) {
        int gr = row0 + ty * 4 + i;
        if (gr < N_NODES) {
            float s = diss[ty * 4 + i];
            float* oh = g_h2 + (size_t)gr * F_OUT + tx * 5;
            float* oo = out  + (size_t)gr * F_OUT + tx * 5;
            #pragma unroll
            for (int j = 0; j < 5; j++) {
                float v = acc[i][j];
                oh[j] = v;
                oo[j] = b2[tx * 5 + j] + s * v;   // self-loop + bias init
            }
        }
    }
}

// Layer-2 edge aggregation: 10 float4 per edge
__global__ void k_agg2(const int* __restrict__ ei,
                       const float* __restrict__ ew,
                       float* __restrict__ out, int E) {
    int idx = blockIdx.x * blockDim.x + threadIdx.x;
    int e = idx / 10;
    int c = idx - e * 10;
    if (e >= E) return;
    int r   = ei[e];
    int col = ei[E + e];
    float nrm = g_dis[r] * ew[e] * g_dis[col];
    float4 v = *(const float4*)(g_h2 + (size_t)r * F_OUT + c * 4);
    atomicAdd((float4*)(out + (size_t)col * F_OUT + c * 4),
              make_float4(nrm * v.x, nrm * v.y, nrm * v.z, nrm * v.w));
}

// ---------------------------------------------------------------------------
extern "C" void kernel_launch(void* const* d_in, const int* in_sizes, int n_in,
                              void* d_out, int out_size) {
    const float* x  = (const float*)d_in[0];
    const int*   ei = (const int*)d_in[1];
    const float* ew = (const float*)d_in[2];
    const float* W1 = (const float*)d_in[3];
    const float* b1 = (const float*)d_in[4];
    const float* W2 = (const float*)d_in[5];
    const float* b2 = (const float*)d_in[6];
    float* out = (float*)d_out;

    int N = in_sizes[0] / F_IN;     // 100000
    int E = in_sizes[2];            // 1600000

    k_zero_deg<<<(N + 255) / 256, 256>>>(N);
    k_deg<<<(E + 255) / 256, 256>>>(ei, ew, E);
    k_dis<<<(N + 255) / 256, 256>>>(N);

    k_gemm1<<<(N + G1_ROWS - 1) / G1_ROWS, 256>>>(x, W1);

    int n1_4 = N * F_HID / 4;
    k_zero_agg1<<<(n1_4 + 255) / 256, 256>>>(n1_4);
    {
        long long items = (long long)E * 16;
        k_agg1<<<(int)((items + 255) / 256), 256>>>(ei, ew, E);
    }

    k_gemm2<<<(N + G2_ROWS - 1) / G2_ROWS, 256>>>(W2, b1, b2, out);

    {
        long long items = (long long)E * 10;
        k_agg2<<<(int)((items + 255) / 256), 256>>>(ei, ew, out, E);
    }
}

// round 6
// speedup vs baseline: 1.0879x; 1.0879x over previous
#include <cuda_runtime.h>

#define N_NODES 100000
#define F_IN    256
#define F_HID   64
#define F_OUT   40

// Scratch (static device globals — no allocation allowed)
__device__ float g_dis[N_NODES];              // deg accumulator, then rsqrt(deg+1)
__device__ float g_h1[N_NODES * F_HID];       // x @ W1
__device__ float g_agg1[N_NODES * F_HID];     // aggregated layer-1, then relu(...)
__device__ float g_h2[N_NODES * F_OUT];       // relu_out @ W2

// ---------------------------------------------------------------------------
// Packed f32x2 helpers (Blackwell FFMA2 path)
// ---------------------------------------------------------------------------
__device__ __forceinline__ unsigned long long f2pack(float lo, float hi) {
    unsigned long long r;
    asm("mov.b64 %0, {%1, %2};" : "=l"(r) : "f"(lo), "f"(hi));
    return r;
}
__device__ __forceinline__ void f2unpack(unsigned long long v, float& lo, float& hi) {
    asm("mov.b64 {%0, %1}, %2;" : "=f"(lo), "=f"(hi) : "l"(v));
}
__device__ __forceinline__ void fma2(unsigned long long& d,
                                     unsigned long long a, unsigned long long b) {
    asm("fma.rn.f32x2 %0, %1, %2, %0;" : "+l"(d) : "l"(a), "l"(b));
}
// load 16B of smem as two packed f32x2 (zero pack cost)
__device__ __forceinline__ void lds_v2u64(unsigned long long& a, unsigned long long& b,
                                          const void* p) {
    unsigned s = (unsigned)__cvta_generic_to_shared(p);
    asm volatile("ld.shared.v2.u64 {%0, %1}, [%2];" : "=l"(a), "=l"(b) : "r"(s));
}

// ---------------------------------------------------------------------------
// Degree / normalization
// ---------------------------------------------------------------------------
__global__ void k_zero_deg(int n) {
    int i = blockIdx.x * blockDim.x + threadIdx.x;
    if (i < n) g_dis[i] = 0.0f;
}

__global__ void k_deg(const int* __restrict__ ei,
                      const float* __restrict__ ew, int E) {
    int e = blockIdx.x * blockDim.x + threadIdx.x;
    if (e < E) {
        int c = ei[E + e];
        atomicAdd(&g_dis[c], ew[e]);
    }
}

__global__ void k_dis(int n) {
    int i = blockIdx.x * blockDim.x + threadIdx.x;
    if (i < n) g_dis[i] = rsqrtf(g_dis[i] + 1.0f);   // +1 = self-loop weight
}

// ---------------------------------------------------------------------------
// GEMM1: g_h1[N,64] = x[N,256] @ W1[256,64]
// 256 thr, tile 128 rows x 64 cols, each thread 8 rows x 4 cols via FFMA2:
// row-pairs packed f32x2, 16 FMA2 + 4 packs + 3 LDS per k-step.
// ---------------------------------------------------------------------------
#define G1_ROWS 128
#define G1_KCH  32

__global__ void k_gemm1(const float* __restrict__ x,
                        const float* __restrict__ W1) {
    __shared__ float xs[G1_KCH][G1_ROWS];   // 16 KB, k-major
    __shared__ float ws[G1_KCH][F_HID];     // 8 KB,  k-major

    int t    = threadIdx.x;
    int row0 = blockIdx.x * G1_ROWS;
    int tx   = t & 15;        // col group: cols tx*4 .. +3
    int ty   = t >> 4;        // row group: rows ty*8 .. +7

    // acc2[p][j]: rows (ty*8+2p, ty*8+2p+1), col tx*4+j, packed f32x2
    unsigned long long acc2[4][4];
    #pragma unroll
    for (int p = 0; p < 4; p++)
        #pragma unroll
        for (int j = 0; j < 4; j++) acc2[p][j] = f2pack(0.0f, 0.0f);

    for (int kc = 0; kc < F_IN / G1_KCH; kc++) {
        // W chunk: 32x64 floats = 512 float4 (W1 is k-major already)
        const float4* w4 = (const float4*)(W1 + kc * G1_KCH * F_HID);
        ((float4*)ws)[t]       = w4[t];
        ((float4*)ws)[t + 256] = w4[t + 256];
        // x tile: 128 rows x 32 k = 1024 float4, transposed into xs[k][row]
        #pragma unroll
        for (int j = 0; j < 4; j++) {
            int idx = t + j * 256;
            int r   = idx & 127;
            int kq  = idx >> 7;                  // 0..7
            int gr  = row0 + r;
            if (gr >= N_NODES) gr = N_NODES - 1; // clamped read (result discarded)
            float4 v = *(const float4*)(x + (size_t)gr * F_IN + kc * G1_KCH + kq * 4);
            xs[kq * 4 + 0][r] = v.x;
            xs[kq * 4 + 1][r] = v.y;
            xs[kq * 4 + 2][r] = v.z;
            xs[kq * 4 + 3][r] = v.w;
        }
        __syncthreads();

        #pragma unroll
        for (int kk = 0; kk < G1_KCH; kk++) {
            unsigned long long ap0, ap1, ap2, ap3;
            lds_v2u64(ap0, ap1, &xs[kk][ty * 8]);
            lds_v2u64(ap2, ap3, &xs[kk][ty * 8 + 4]);
            float4 b = *(const float4*)&ws[kk][tx * 4];
            unsigned long long bd0 = f2pack(b.x, b.x);
            unsigned long long bd1 = f2pack(b.y, b.y);
            unsigned long long bd2 = f2pack(b.z, b.z);
            unsigned long long bd3 = f2pack(b.w, b.w);
            fma2(acc2[0][0], ap0, bd0); fma2(acc2[0][1], ap0, bd1);
            fma2(acc2[0][2], ap0, bd2); fma2(acc2[0][3], ap0, bd3);
            fma2(acc2[1][0], ap1, bd0); fma2(acc2[1][1], ap1, bd1);
            fma2(acc2[1][2], ap1, bd2); fma2(acc2[1][3], ap1, bd3);
            fma2(acc2[2][0], ap2, bd0); fma2(acc2[2][1], ap2, bd1);
            fma2(acc2[2][2], ap2, bd2); fma2(acc2[2][3], ap2, bd3);
            fma2(acc2[3][0], ap3, bd0); fma2(acc2[3][1], ap3, bd1);
            fma2(acc2[3][2], ap3, bd2); fma2(acc2[3][3], ap3, bd3);
        }
        __syncthreads();
    }

    #pragma unroll
    for (int p = 0; p < 4; p++) {
        float lo0, hi0, lo1, hi1, lo2, hi2, lo3, hi3;
        f2unpack(acc2[p][0], lo0, hi0);
        f2unpack(acc2[p][1], lo1, hi1);
        f2unpack(acc2[p][2], lo2, hi2);
        f2unpack(acc2[p][3], lo3, hi3);
        int gr0 = row0 + ty * 8 + 2 * p;
        if (gr0 < N_NODES)
            *(float4*)(g_h1 + (size_t)gr0 * F_HID + tx * 4) =
                make_float4(lo0, lo1, lo2, lo3);
        if (gr0 + 1 < N_NODES)
            *(float4*)(g_h1 + (size_t)(gr0 + 1) * F_HID + tx * 4) =
                make_float4(hi0, hi1, hi2, hi3);
    }
}

// ---------------------------------------------------------------------------
// Layer-1 edge aggregation: 16 threads per edge, float4 vectorized atomics
// ---------------------------------------------------------------------------
__global__ void k_zero_agg1(int n4) {
    int i = blockIdx.x * blockDim.x + threadIdx.x;
    if (i < n4) ((float4*)g_agg1)[i] = make_float4(0.f, 0.f, 0.f, 0.f);
}

__global__ void k_agg1(const int* __restrict__ ei,
                       const float* __restrict__ ew, int E) {
    int idx = blockIdx.x * blockDim.x + threadIdx.x;
    int e = idx >> 4;
    int c = idx & 15;
    if (e >= E) return;
    int r   = ei[e];
    int col = ei[E + e];
    float nrm = g_dis[r] * ew[e] * g_dis[col];
    float4 v = *(const float4*)(g_h1 + (size_t)r * F_HID + c * 4);
    atomicAdd((float4*)(g_agg1 + (size_t)col * F_HID + c * 4),
              make_float4(nrm * v.x, nrm * v.y, nrm * v.z, nrm * v.w));
}

// self loop + bias + relu, in place into g_agg1 (float4)
__global__ void k_selfrelu(const float* __restrict__ b1, int n4) {
    int idx4 = blockIdx.x * blockDim.x + threadIdx.x;
    if (idx4 >= n4) return;
    int i  = idx4 >> 4;          // node (16 float4 per row)
    int f4 = idx4 & 15;
    float d = g_dis[i];
    float s = d * d;
    float4 a = ((const float4*)g_agg1)[idx4];
    float4 h = ((const float4*)g_h1)[idx4];
    float4 b = ((const float4*)b1)[f4];
    float4 o;
    o.x = fmaxf(a.x + s * h.x + b.x, 0.0f);
    o.y = fmaxf(a.y + s * h.y + b.y, 0.0f);
    o.z = fmaxf(a.z + s * h.z + b.z, 0.0f);
    o.w = fmaxf(a.w + s * h.w + b.w, 0.0f);
    ((float4*)g_agg1)[idx4] = o;
}

// ---------------------------------------------------------------------------
// GEMM2: g_h2[N,40] = relu_out[N,64] @ W2[64,40]
// 256 thr, tile 128 rows x 40 cols, each thread 4x5 via FFMA2 row-pairs.
// ---------------------------------------------------------------------------
#define G2_ROWS 128

__global__ void k_gemm2(const float* __restrict__ W2) {
    __shared__ float rs[F_HID][G2_ROWS];   // 32 KB, k-major
    __shared__ float ws2[F_HID][F_OUT];    // 10 KB

    int t    = threadIdx.x;
    int row0 = blockIdx.x * G2_ROWS;
    int tx   = t & 7;         // col group: cols tx*5 .. +4
    int ty   = t >> 3;        // row group: rows ty*4 .. +3

    // load W2 (2560 floats = 640 float4)
    #pragma unroll
    for (int j = 0; j < 3; j++) {
        int i = t + j * 256;
        if (i < 640) ((float4*)ws2)[i] = ((const float4*)W2)[i];
    }
    // load relu tile: 128 rows x 64 k = 2048 float4, transposed
    #pragma unroll
    for (int j = 0; j < 8; j++) {
        int idx = t + j * 256;
        int r   = idx & 127;
        int kq  = idx >> 7;                   // 0..15
        int gr  = row0 + r;
        if (gr >= N_NODES) gr = N_NODES - 1;
        float4 v = *(const float4*)(g_agg1 + (size_t)gr * F_HID + kq * 4);
        rs[kq * 4 + 0][r] = v.x;
        rs[kq * 4 + 1][r] = v.y;
        rs[kq * 4 + 2][r] = v.z;
        rs[kq * 4 + 3][r] = v.w;
    }
    __syncthreads();

    // acc2[p][j]: rows (ty*4+2p, ty*4+2p+1), col tx*5+j
    unsigned long long acc2[2][5];
    #pragma unroll
    for (int p = 0; p < 2; p++)
        #pragma unroll
        for (int j = 0; j < 5; j++) acc2[p][j] = f2pack(0.0f, 0.0f);

    #pragma unroll
    for (int kk = 0; kk < F_HID; kk++) {
        unsigned long long ap0, ap1;
        lds_v2u64(ap0, ap1, &rs[kk][ty * 4]);
        const float* wrow = &ws2[kk][tx * 5];
        #pragma unroll
        for (int j = 0; j < 5; j++) {
            float bj = wrow[j];
            unsigned long long bd = f2pack(bj, bj);
            fma2(acc2[0][j], ap0, bd);
            fma2(acc2[1][j], ap1, bd);
        }
    }

    #pragma unroll
    for (int p = 0; p < 2; p++) {
        float lo[5], hi[5];
        #pragma unroll
        for (int j = 0; j < 5; j++) f2unpack(acc2[p][j], lo[j], hi[j]);
        int gr0 = row0 + ty * 4 + 2 * p;
        if (gr0 < N_NODES) {
            float* o = g_h2 + (size_t)gr0 * F_OUT + tx * 5;
            #pragma unroll
            for (int j = 0; j < 5; j++) o[j] = lo[j];
        }
        if (gr0 + 1 < N_NODES) {
            float* o = g_h2 + (size_t)(gr0 + 1) * F_OUT + tx * 5;
            #pragma unroll
            for (int j = 0; j < 5; j++) o[j] = hi[j];
        }
    }
}

// init output with bias + self-loop contribution (float4, 10 per row)
__global__ void k_init_out(const float* __restrict__ b2,
                           float* __restrict__ out, int n4) {
    int idx4 = blockIdx.x * blockDim.x + threadIdx.x;
    if (idx4 >= n4) return;
    int i  = idx4 / 10;
    int f4 = idx4 - i * 10;
    float d = g_dis[i];
    float s = d * d;
    float4 h = ((const float4*)g_h2)[idx4];
    float4 b = ((const float4*)b2)[f4];
    ((float4*)out)[idx4] =
        make_float4(b.x + s * h.x, b.y + s * h.y, b.z + s * h.z, b.w + s * h.w);
}

// Layer-2 edge aggregation: 10 float4 per edge
__global__ void k_agg2(const int* __restrict__ ei,
                       const float* __restrict__ ew,
                       float* __restrict__ out, int E) {
    int idx = blockIdx.x * blockDim.x + threadIdx.x;
    int e = idx / 10;
    int c = idx - e * 10;
    if (e >= E) return;
    int r   = ei[e];
    int col = ei[E + e];
    float nrm = g_dis[r] * ew[e] * g_dis[col];
    float4 v = *(const float4*)(g_h2 + (size_t)r * F_OUT + c * 4);
    atomicAdd((float4*)(out + (size_t)col * F_OUT + c * 4),
              make_float4(nrm * v.x, nrm * v.y, nrm * v.z, nrm * v.w));
}

// ---------------------------------------------------------------------------
extern "C" void kernel_launch(void* const* d_in, const int* in_sizes, int n_in,
                              void* d_out, int out_size) {
    const float* x  = (const float*)d_in[0];
    const int*   ei = (const int*)d_in[1];
    const float* ew = (const float*)d_in[2];
    const float* W1 = (const float*)d_in[3];
    const float* b1 = (const float*)d_in[4];
    const float* W2 = (const float*)d_in[5];
    const float* b2 = (const float*)d_in[6];
    float* out = (float*)d_out;

    int N = in_sizes[0] / F_IN;     // 100000
    int E = in_sizes[2];            // 1600000

    k_zero_deg<<<(N + 255) / 256, 256>>>(N);
    k_deg<<<(E + 255) / 256, 256>>>(ei, ew, E);
    k_dis<<<(N + 255) / 256, 256>>>(N);

    int gemm_grid = (N + G1_ROWS - 1) / G1_ROWS;   // 782
    k_gemm1<<<gemm_grid, 256>>>(x, W1);

    int n1_4 = N * F_HID / 4;
    k_zero_agg1<<<(n1_4 + 255) / 256, 256>>>(n1_4);
    {
        long long items = (long long)E * 16;
        k_agg1<<<(int)((items + 255) / 256), 256>>>(ei, ew, E);
    }
    k_selfrelu<<<(n1_4 + 255) / 256, 256>>>(b1, n1_4);

    k_gemm2<<<gemm_grid, 256>>>(W2);

    int n2_4 = N * F_OUT / 4;
    k_init_out<<<(n2_4 + 255) / 256, 256>>>(b2, out, n2_4);
    {
        long long items = (long long)E * 10;
        k_agg2<<<(int)((items + 255) / 256), 256>>>(ei, ew, out, E);
    }
}